// round 12
// baseline (speedup 1.0000x reference)
#include <cuda_runtime.h>
#include <cuda_bf16.h>
#include <cstdint>

#define NTOK 16384
#define DMODEL 2048
#define NGRP 8
#define HDG 256
#define DH 512   // k * hdg
#define TOKPB 8  // tokens per gate block

// ---------------- scratch (no allocs allowed) ----------------
__device__ __align__(16) __nv_bfloat16 g_hin[(size_t)NTOK * DH];   // 16 MB gathered, gated inputs
__device__ __align__(16) __nv_bfloat16 g_wm[(size_t)DH * DH];      // 512 KB bf16 weights ([k][n])
__device__ int g_idx[NTOK * 2];                                    // top-2 group indices per token

extern __shared__ __align__(16) unsigned char dynsmem[];

// ---------------- kernel 1: gate + gather + PDL trigger + selective passthrough ------------
// R6 champion layout: 8 tokens/block, 512 threads, thread owns ONE gate group
// (tid&7) and 32 x-elements (s=tid>>3); 2 shuffles/warp/token reduce.
// New: gather + g_idx land BEFORE the trigger; passthrough (out writes) after,
// so the dependent GEMM grid can launch while the last wave drains.
__global__ __launch_bounds__(512, 2) void gate_kernel(const float* __restrict__ x,
                                                      const float* __restrict__ Wg,
                                                      const float* __restrict__ Wm,
                                                      float* __restrict__ out) {
    float* xs = (float*)dynsmem;                      // [TOKPB][DMODEL] fp32
    __shared__ float wsum[TOKPB][16][NGRP];
    __shared__ float sG[TOKPB][2];
    __shared__ int   sI[TOKPB][2];

    const int tid  = threadIdx.x;
    const int lane = tid & 31;
    const int warp = tid >> 5;
    const int g    = tid & 7;    // this thread's gate group
    const int s    = tid >> 3;   // element-slice index, 0..63
    const size_t tok0 = (size_t)blockIdx.x * TOKPB;

    // stage 8 token rows via cp.async in two 32KB halves (tokens 0-3, 4-7)
    const uint32_t sx = (uint32_t)__cvta_generic_to_shared(xs);
    const float* src0 = x + tok0 * DMODEL;
#pragma unroll
    for (int i = 0; i < 4; i++) {
        int q = tid + i * 512;
        asm volatile("cp.async.cg.shared.global [%0], [%1], 16;\n"
                     :: "r"(sx + q * 16), "l"(src0 + q * 4));
    }
    asm volatile("cp.async.commit_group;\n");
#pragma unroll
    for (int i = 0; i < 4; i++) {
        int q = 2048 + tid + i * 512;
        asm volatile("cp.async.cg.shared.global [%0], [%1], 16;\n"
                     :: "r"(sx + q * 16), "l"(src0 + q * 4));
    }
    asm volatile("cp.async.commit_group;\n");

    // folded Wm fp32 -> bf16 conversion (blocks 0..511 cover all of Wm)
    if (blockIdx.x < 512) {
        int i = blockIdx.x * 512 + tid;
        g_wm[i] = __float2bfloat16(Wm[i]);
    }

    // Wg column-slice register cache: Wg[e][g] for e = k*256 + s*4 + c  (32 regs)
    float wgc[32];
#pragma unroll
    for (int k = 0; k < 8; k++)
#pragma unroll
        for (int c = 0; c < 4; c++)
            wgc[k * 4 + c] = __ldg(Wg + (size_t)(k * 256 + s * 4 + c) * NGRP + g);

    // first half arrived -> logits for tokens 0-3 while 4-7 still loading
    asm volatile("cp.async.wait_group 1;\n");
    __syncthreads();

#pragma unroll 2
    for (int t = 0; t < TOKPB / 2; t++) {
        const float4* xt = (const float4*)(xs + t * DMODEL);
        float a0 = 0.f, a1 = 0.f, a2 = 0.f, a3 = 0.f;
#pragma unroll
        for (int k = 0; k < 8; k++) {
            float4 v = xt[k * 64 + s];           // broadcast across 8 same-s lanes
            a0 += v.x * wgc[k * 4 + 0];
            a1 += v.y * wgc[k * 4 + 1];
            a2 += v.z * wgc[k * 4 + 2];
            a3 += v.w * wgc[k * 4 + 3];
        }
        float p = (a0 + a1) + (a2 + a3);
        p += __shfl_xor_sync(0xffffffffu, p, 8);
        p += __shfl_xor_sync(0xffffffffu, p, 16);
        if (lane < NGRP) wsum[t][warp][lane] = p;   // lane==g for lane<8
    }

    asm volatile("cp.async.wait_group 0;\n");
    __syncthreads();

#pragma unroll 2
    for (int t = TOKPB / 2; t < TOKPB; t++) {
        const float4* xt = (const float4*)(xs + t * DMODEL);
        float a0 = 0.f, a1 = 0.f, a2 = 0.f, a3 = 0.f;
#pragma unroll
        for (int k = 0; k < 8; k++) {
            float4 v = xt[k * 64 + s];
            a0 += v.x * wgc[k * 4 + 0];
            a1 += v.y * wgc[k * 4 + 1];
            a2 += v.z * wgc[k * 4 + 2];
            a3 += v.w * wgc[k * 4 + 3];
        }
        float p = (a0 + a1) + (a2 + a3);
        p += __shfl_xor_sync(0xffffffffu, p, 8);
        p += __shfl_xor_sync(0xffffffffu, p, 16);
        if (lane < NGRP) wsum[t][warp][lane] = p;
    }
    __syncthreads();

    // parallel partial reduce: 64 threads, one (token, group) pair each
    if (tid < 64) {
        int t = tid >> 3, j = tid & 7;
        float sum = 0.f;
#pragma unroll
        for (int w = 0; w < 16; w++) sum += wsum[t][w][j];
        wsum[t][0][j] = sum;
    }
    __syncthreads();

    // softmax + top-2, one token per lane (8 values each)
    if (tid < TOKPB) {
        int t = tid;
        float l[NGRP];
#pragma unroll
        for (int j = 0; j < NGRP; j++) l[j] = wsum[t][0][j];
        float m = l[0];
#pragma unroll
        for (int j = 1; j < NGRP; j++) m = fmaxf(m, l[j]);
        float e[NGRP], ssum = 0.f;
#pragma unroll
        for (int j = 0; j < NGRP; j++) { e[j] = expf(l[j] - m); ssum += e[j]; }
        int i0 = 0;
#pragma unroll
        for (int j = 1; j < NGRP; j++) if (e[j] > e[i0]) i0 = j;
        int i1 = (i0 == 0) ? 1 : 0;
#pragma unroll
        for (int j = 0; j < NGRP; j++) if (j != i0 && e[j] > e[i1]) i1 = j;
        float inv = 1.f / ssum;
        sG[t][0] = e[i0] * inv;  sG[t][1] = e[i1] * inv;
        sI[t][0] = i0;           sI[t][1] = i1;
        g_idx[(tok0 + t) * 2 + 0] = i0;
        g_idx[(tok0 + t) * 2 + 1] = i1;
    }
    __syncthreads();

    // gather + gate -> g_hin FIRST (GEMM inputs): 2 tokens per pass
#pragma unroll
    for (int it = 0; it < 4; it++) {
        int tloc = it * 2 + (tid >> 8);
        int p    = tid & 255;
        int half = p >> 7;
        float gate = sG[tloc][half];
        int base2 = sI[tloc][half] * (HDG / 2) + (p & 127);
        float2 xv = ((const float2*)(xs + tloc * DMODEL))[base2];
        ((__nv_bfloat162*)g_hin)[(tok0 + tloc) * (DH / 2) + p] =
            __floats2bfloat162_rn(gate * xv.x, gate * xv.y);
    }

    // publish g_hin / g_idx / g_wm, then signal PDL trigger
    __threadfence();
    __syncthreads();
    if (tid == 0)
        asm volatile("griddepcontrol.launch_dependents;" ::: "memory");

    // passthrough (skip selected groups; GEMM writes those) AFTER the trigger
#pragma unroll 1
    for (int t = 0; t < TOKPB; t++) {
        int i0 = sI[t][0], i1 = sI[t][1];
        int grp = tid >> 6;
        if (grp != i0 && grp != i1) {
            float4* orow = (float4*)(out + (tok0 + t) * DMODEL);
            __stcs(&orow[tid], ((const float4*)(xs + t * DMODEL))[tid]);
        }
    }
}

// ---------------- kernel 2: GEMM [16384,512]x[512,512] bf16 -> fp32, scatter epilogue --------
// BM=128, BN=64, BK=64, 256 threads, 3-stage cp.async pipeline, 72KB dynamic smem.
// (R3/R5/R6 configuration: measured 29.5-30.1us). PDL-dependent.
#define BM 128
#define BN 64
#define BK 64
#define STAGE_BYTES (BM * BK * 2 + BK * BN * 2)   // 16KB + 8KB = 24KB

__device__ __forceinline__ uint32_t sw_off(uint32_t row, uint32_t g) {
    return row * 128u + ((g ^ (row & 7u)) * 16u);
}

__global__ __launch_bounds__(256) void gemm_scatter(const float* __restrict__ bias,
                                                    float* __restrict__ out) {
    // wait for the gate grid's trigger (returns immediately in practice:
    // the dependent grid only launches once all primaries have triggered)
    asm volatile("griddepcontrol.wait;" ::: "memory");

    const int tid  = threadIdx.x;
    const int lane = tid & 31;
    const int warp = tid >> 5;
    const int wm   = warp >> 1;
    const int wn   = warp & 1;
    const int bn   = blockIdx.x;  // 0..7
    const int bm   = blockIdx.y;  // 0..127

    const __nv_bfloat16* Ag = g_hin + (size_t)(bm * BM) * DH;
    const __nv_bfloat16* Bg = g_wm + (size_t)(bn * BN);

    const uint32_t sBase = (uint32_t)__cvta_generic_to_shared(dynsmem);

    auto load_stage = [&](int s, int kt) {
        uint32_t sA = sBase + s * STAGE_BYTES;
        uint32_t sB = sA + BM * BK * 2;
#pragma unroll
        for (int i = 0; i < 4; i++) {
            int q = tid + i * 256;
            int r = q >> 3, g = q & 7;
            const __nv_bfloat16* src = Ag + (size_t)r * DH + kt + g * 8;
            asm volatile("cp.async.cg.shared.global [%0], [%1], 16;\n"
                         :: "r"(sA + sw_off(r, g)), "l"(src));
        }
#pragma unroll
        for (int i = 0; i < 2; i++) {
            int q = tid + i * 256;
            int r = q >> 3, g = q & 7;
            const __nv_bfloat16* src = Bg + (size_t)(kt + r) * DH + g * 8;
            asm volatile("cp.async.cg.shared.global [%0], [%1], 16;\n"
                         :: "r"(sB + sw_off(r, g)), "l"(src));
        }
        asm volatile("cp.async.commit_group;\n");
    };

    float acc[2][4][4];
#pragma unroll
    for (int a = 0; a < 2; a++)
#pragma unroll
        for (int b = 0; b < 4; b++)
#pragma unroll
            for (int c = 0; c < 4; c++) acc[a][b][c] = 0.f;

    const int NKT = DH / BK;   // 8
    load_stage(0, 0);
    load_stage(1, BK);

    for (int k = 0; k < NKT; k++) {
        if (k < NKT - 1) asm volatile("cp.async.wait_group 1;\n");
        else             asm volatile("cp.async.wait_group 0;\n");
        __syncthreads();

        if (k + 2 < NKT) load_stage((k + 2) % 3, (k + 2) * BK);

        uint32_t sA = sBase + (k % 3) * STAGE_BYTES;
        uint32_t sB = sA + BM * BK * 2;
#pragma unroll
        for (int ks = 0; ks < 4; ks++) {
            uint32_t a[2][4];
#pragma unroll
            for (int mt = 0; mt < 2; mt++) {
                uint32_t row = wm * 32 + mt * 16 + (lane & 15);
                uint32_t gg  = ks * 2 + (lane >> 4);
                uint32_t addr = sA + sw_off(row, gg);
                asm volatile(
                    "ldmatrix.sync.aligned.m8n8.x4.shared.b16 {%0,%1,%2,%3}, [%4];"
                    : "=r"(a[mt][0]), "=r"(a[mt][1]), "=r"(a[mt][2]), "=r"(a[mt][3])
                    : "r"(addr));
            }
            uint32_t b[4][2];
#pragma unroll
            for (int half = 0; half < 2; half++) {
                uint32_t row = ks * 16 + (lane & 15);
                uint32_t gg  = wn * 4 + half * 2 + (lane >> 4);
                uint32_t addr = sB + sw_off(row, gg);
                uint32_t r0, r1, r2, r3;
                asm volatile(
                    "ldmatrix.sync.aligned.m8n8.x4.trans.shared.b16 {%0,%1,%2,%3}, [%4];"
                    : "=r"(r0), "=r"(r1), "=r"(r2), "=r"(r3)
                    : "r"(addr));
                b[half * 2 + 0][0] = r0; b[half * 2 + 0][1] = r1;
                b[half * 2 + 1][0] = r2; b[half * 2 + 1][1] = r3;
            }
#pragma unroll
            for (int mt = 0; mt < 2; mt++)
#pragma unroll
                for (int nt = 0; nt < 4; nt++) {
                    asm volatile(
                        "mma.sync.aligned.m16n8k16.row.col.f32.bf16.bf16.f32 "
                        "{%0,%1,%2,%3}, {%4,%5,%6,%7}, {%8,%9}, {%0,%1,%2,%3};"
                        : "+f"(acc[mt][nt][0]), "+f"(acc[mt][nt][1]),
                          "+f"(acc[mt][nt][2]), "+f"(acc[mt][nt][3])
                        : "r"(a[mt][0]), "r"(a[mt][1]), "r"(a[mt][2]), "r"(a[mt][3]),
                          "r"(b[nt][0]), "r"(b[nt][1]));
                }
        }
    }

    const int gsel = bn >> 2;
#pragma unroll
    for (int mt = 0; mt < 2; mt++) {
#pragma unroll
        for (int rr = 0; rr < 2; rr++) {
            int tok = bm * BM + wm * 32 + mt * 16 + (lane >> 2) + rr * 8;
            int grp = g_idx[tok * 2 + gsel];
            float* orow = out + (size_t)tok * DMODEL + grp * HDG;
#pragma unroll
            for (int nt = 0; nt < 4; nt++) {
                int c  = bn * BN + wn * 32 + nt * 8 + (lane & 3) * 2;
                int cl = c & (HDG - 1);
                float2 bv = *(const float2*)(bias + c);
                float2 v;
                v.x = acc[mt][nt][rr * 2 + 0] + bv.x;
                v.y = acc[mt][nt][rr * 2 + 1] + bv.y;
                *(float2*)(orow + cl) = v;
            }
        }
    }
}

// ---------------- launch ----------------
extern "C" void kernel_launch(void* const* d_in, const int* in_sizes, int n_in,
                              void* d_out, int out_size) {
    const float* x    = (const float*)d_in[0];
    const float* Wg   = (const float*)d_in[1];
    const float* Wm   = (const float*)d_in[2];
    const float* bias = (const float*)d_in[3];
    float* out = (float*)d_out;

    static bool attr_done = false;
    if (!attr_done) {
        cudaFuncSetAttribute(gate_kernel,
                             cudaFuncAttributeMaxDynamicSharedMemorySize, TOKPB * DMODEL * 4);
        cudaFuncSetAttribute(gemm_scatter,
                             cudaFuncAttributeMaxDynamicSharedMemorySize, 3 * STAGE_BYTES);
        attr_done = true;
    }

    gate_kernel<<<NTOK / TOKPB, 512, TOKPB * DMODEL * 4>>>(x, Wg, Wm, out);

    // GEMM launched as a programmatic dependent of the gate kernel
    cudaLaunchConfig_t cfg = {};
    cfg.gridDim = dim3(DH / BN, NTOK / BM, 1);
    cfg.blockDim = dim3(256, 1, 1);
    cfg.dynamicSmemBytes = 3 * STAGE_BYTES;
    cfg.stream = 0;
    cudaLaunchAttribute attrs[1];
    attrs[0].id = cudaLaunchAttributeProgrammaticStreamSerialization;
    attrs[0].val.programmaticStreamSerializationAllowed = 1;
    cfg.attrs = attrs;
    cfg.numAttrs = 1;
    cudaLaunchKernelEx(&cfg, gemm_scatter, bias, out);
}

// round 13
// speedup vs baseline: 1.1188x; 1.1188x over previous
#include <cuda_runtime.h>
#include <cuda_bf16.h>
#include <cstdint>

#define NTOK 16384
#define DMODEL 2048
#define NGRP 8
#define HDG 256
#define DH 512   // k * hdg
#define TOKPB 8  // tokens per gate block

// ---------------- scratch (no allocs allowed) ----------------
__device__ __align__(16) __nv_bfloat16 g_hin[(size_t)NTOK * DH];   // 16 MB gathered, gated inputs
__device__ __align__(16) __nv_bfloat16 g_wm[(size_t)DH * DH];      // 512 KB bf16 weights ([k][n])
__device__ int g_idx[NTOK * 2];                                    // top-2 group indices per token

extern __shared__ __align__(16) unsigned char dynsmem[];

// ---------------- kernel 1 (R6 champion + parallel reduce): gate + passthrough + gather ----
// 8 tokens/block, 512 threads. Thread owns ONE gate group (tid&7) and 32
// x-elements (s=tid>>3): reduce needs only 2 shuffles/warp/token.
__global__ __launch_bounds__(512, 2) void gate_kernel(const float* __restrict__ x,
                                                      const float* __restrict__ Wg,
                                                      const float* __restrict__ Wm,
                                                      float* __restrict__ out) {
    float* xs = (float*)dynsmem;                      // [TOKPB][DMODEL] fp32
    __shared__ float wsum[TOKPB][16][NGRP];
    __shared__ float sG[TOKPB][2];
    __shared__ int   sI[TOKPB][2];

    const int tid  = threadIdx.x;
    const int lane = tid & 31;
    const int warp = tid >> 5;
    const int g    = tid & 7;    // this thread's gate group
    const int s    = tid >> 3;   // element-slice index, 0..63
    const size_t tok0 = (size_t)blockIdx.x * TOKPB;

    // stage 8 token rows via cp.async in two 32KB halves (tokens 0-3, 4-7)
    const uint32_t sx = (uint32_t)__cvta_generic_to_shared(xs);
    const float* src0 = x + tok0 * DMODEL;
#pragma unroll
    for (int i = 0; i < 4; i++) {
        int q = tid + i * 512;
        asm volatile("cp.async.cg.shared.global [%0], [%1], 16;\n"
                     :: "r"(sx + q * 16), "l"(src0 + q * 4));
    }
    asm volatile("cp.async.commit_group;\n");
#pragma unroll
    for (int i = 0; i < 4; i++) {
        int q = 2048 + tid + i * 512;
        asm volatile("cp.async.cg.shared.global [%0], [%1], 16;\n"
                     :: "r"(sx + q * 16), "l"(src0 + q * 4));
    }
    asm volatile("cp.async.commit_group;\n");

    // folded Wm fp32 -> bf16 conversion (blocks 0..511 cover all of Wm)
    if (blockIdx.x < 512) {
        int i = blockIdx.x * 512 + tid;
        g_wm[i] = __float2bfloat16(Wm[i]);
    }

    // Wg column-slice register cache: Wg[e][g] for e = k*256 + s*4 + c  (32 regs)
    float wgc[32];
#pragma unroll
    for (int k = 0; k < 8; k++)
#pragma unroll
        for (int c = 0; c < 4; c++)
            wgc[k * 4 + c] = __ldg(Wg + (size_t)(k * 256 + s * 4 + c) * NGRP + g);

    // first half arrived -> logits for tokens 0-3 while 4-7 still loading
    asm volatile("cp.async.wait_group 1;\n");
    __syncthreads();

#pragma unroll 2
    for (int t = 0; t < TOKPB / 2; t++) {
        const float4* xt = (const float4*)(xs + t * DMODEL);
        float a0 = 0.f, a1 = 0.f, a2 = 0.f, a3 = 0.f;
#pragma unroll
        for (int k = 0; k < 8; k++) {
            float4 v = xt[k * 64 + s];           // broadcast across 8 same-s lanes
            a0 += v.x * wgc[k * 4 + 0];
            a1 += v.y * wgc[k * 4 + 1];
            a2 += v.z * wgc[k * 4 + 2];
            a3 += v.w * wgc[k * 4 + 3];
        }
        float p = (a0 + a1) + (a2 + a3);
        p += __shfl_xor_sync(0xffffffffu, p, 8);
        p += __shfl_xor_sync(0xffffffffu, p, 16);
        if (lane < NGRP) wsum[t][warp][lane] = p;   // lane==g for lane<8
    }

    asm volatile("cp.async.wait_group 0;\n");
    __syncthreads();

#pragma unroll 2
    for (int t = TOKPB / 2; t < TOKPB; t++) {
        const float4* xt = (const float4*)(xs + t * DMODEL);
        float a0 = 0.f, a1 = 0.f, a2 = 0.f, a3 = 0.f;
#pragma unroll
        for (int k = 0; k < 8; k++) {
            float4 v = xt[k * 64 + s];
            a0 += v.x * wgc[k * 4 + 0];
            a1 += v.y * wgc[k * 4 + 1];
            a2 += v.z * wgc[k * 4 + 2];
            a3 += v.w * wgc[k * 4 + 3];
        }
        float p = (a0 + a1) + (a2 + a3);
        p += __shfl_xor_sync(0xffffffffu, p, 8);
        p += __shfl_xor_sync(0xffffffffu, p, 16);
        if (lane < NGRP) wsum[t][warp][lane] = p;
    }
    __syncthreads();

    // parallel partial reduce: 64 threads, one (token, group) pair each
    if (tid < 64) {
        int t = tid >> 3, j = tid & 7;
        float sum = 0.f;
#pragma unroll
        for (int w = 0; w < 16; w++) sum += wsum[t][w][j];
        wsum[t][0][j] = sum;
    }
    __syncthreads();

    // softmax + top-2, one token per lane (8 values each)
    if (tid < TOKPB) {
        int t = tid;
        float l[NGRP];
#pragma unroll
        for (int j = 0; j < NGRP; j++) l[j] = wsum[t][0][j];
        float m = l[0];
#pragma unroll
        for (int j = 1; j < NGRP; j++) m = fmaxf(m, l[j]);
        float e[NGRP], ssum = 0.f;
#pragma unroll
        for (int j = 0; j < NGRP; j++) { e[j] = expf(l[j] - m); ssum += e[j]; }
        int i0 = 0;
#pragma unroll
        for (int j = 1; j < NGRP; j++) if (e[j] > e[i0]) i0 = j;
        int i1 = (i0 == 0) ? 1 : 0;
#pragma unroll
        for (int j = 0; j < NGRP; j++) if (j != i0 && e[j] > e[i1]) i1 = j;
        float inv = 1.f / ssum;
        sG[t][0] = e[i0] * inv;  sG[t][1] = e[i1] * inv;
        sI[t][0] = i0;           sI[t][1] = i1;
        g_idx[(tok0 + t) * 2 + 0] = i0;
        g_idx[(tok0 + t) * 2 + 1] = i1;
    }
    __syncthreads();

    // passthrough (skip selected groups; GEMM writes those): 1 chunk/thread/token
#pragma unroll 1
    for (int t = 0; t < TOKPB; t++) {
        int i0 = sI[t][0], i1 = sI[t][1];
        int grp = tid >> 6;
        if (grp != i0 && grp != i1) {
            float4* orow = (float4*)(out + (tok0 + t) * DMODEL);
            __stcs(&orow[tid], ((const float4*)(xs + t * DMODEL))[tid]);
        }
    }
    // gather + gate -> g_hin: 2 tokens per pass, 256 threads each
#pragma unroll
    for (int it = 0; it < 4; it++) {
        int tloc = it * 2 + (tid >> 8);
        int p    = tid & 255;
        int half = p >> 7;
        float gate = sG[tloc][half];
        int base2 = sI[tloc][half] * (HDG / 2) + (p & 127);
        float2 xv = ((const float2*)(xs + tloc * DMODEL))[base2];
        ((__nv_bfloat162*)g_hin)[(tok0 + tloc) * (DH / 2) + p] =
            __floats2bfloat162_rn(gate * xv.x, gate * xv.y);
    }
}

// ---------------- kernel 2: GEMM [16384,512]x[512,512] bf16 -> fp32, scatter epilogue --------
// BM=128, BN=64, BK=64, 256 threads, 3-stage cp.async pipeline, 72KB dynamic smem.
// R6 config + fully unrolled k-loop (constant-folds stage indices) + pinned 3 blocks/SM.
#define BM 128
#define BN 64
#define BK 64
#define STAGE_BYTES (BM * BK * 2 + BK * BN * 2)   // 16KB + 8KB = 24KB

__device__ __forceinline__ uint32_t sw_off(uint32_t row, uint32_t g) {
    return row * 128u + ((g ^ (row & 7u)) * 16u);
}

__global__ __launch_bounds__(256, 3) void gemm_scatter(const float* __restrict__ bias,
                                                       float* __restrict__ out) {
    const int tid  = threadIdx.x;
    const int lane = tid & 31;
    const int warp = tid >> 5;
    const int wm   = warp >> 1;
    const int wn   = warp & 1;
    const int bn   = blockIdx.x;  // 0..7
    const int bm   = blockIdx.y;  // 0..127

    const __nv_bfloat16* Ag = g_hin + (size_t)(bm * BM) * DH;
    const __nv_bfloat16* Bg = g_wm + (size_t)(bn * BN);

    const uint32_t sBase = (uint32_t)__cvta_generic_to_shared(dynsmem);

    auto load_stage = [&](int s, int kt) {
        uint32_t sA = sBase + s * STAGE_BYTES;
        uint32_t sB = sA + BM * BK * 2;
#pragma unroll
        for (int i = 0; i < 4; i++) {
            int q = tid + i * 256;
            int r = q >> 3, g = q & 7;
            const __nv_bfloat16* src = Ag + (size_t)r * DH + kt + g * 8;
            asm volatile("cp.async.cg.shared.global [%0], [%1], 16;\n"
                         :: "r"(sA + sw_off(r, g)), "l"(src));
        }
#pragma unroll
        for (int i = 0; i < 2; i++) {
            int q = tid + i * 256;
            int r = q >> 3, g = q & 7;
            const __nv_bfloat16* src = Bg + (size_t)(kt + r) * DH + g * 8;
            asm volatile("cp.async.cg.shared.global [%0], [%1], 16;\n"
                         :: "r"(sB + sw_off(r, g)), "l"(src));
        }
        asm volatile("cp.async.commit_group;\n");
    };

    float acc[2][4][4];
#pragma unroll
    for (int a = 0; a < 2; a++)
#pragma unroll
        for (int b = 0; b < 4; b++)
#pragma unroll
            for (int c = 0; c < 4; c++) acc[a][b][c] = 0.f;

    const int NKT = DH / BK;   // 8
    load_stage(0, 0);
    load_stage(1, BK);

#pragma unroll
    for (int k = 0; k < NKT; k++) {
        if (k < NKT - 1) asm volatile("cp.async.wait_group 1;\n");
        else             asm volatile("cp.async.wait_group 0;\n");
        __syncthreads();

        if (k + 2 < NKT) load_stage((k + 2) % 3, (k + 2) * BK);

        uint32_t sA = sBase + (k % 3) * STAGE_BYTES;
        uint32_t sB = sA + BM * BK * 2;
#pragma unroll
        for (int ks = 0; ks < 4; ks++) {
            uint32_t a[2][4];
#pragma unroll
            for (int mt = 0; mt < 2; mt++) {
                uint32_t row = wm * 32 + mt * 16 + (lane & 15);
                uint32_t gg  = ks * 2 + (lane >> 4);
                uint32_t addr = sA + sw_off(row, gg);
                asm volatile(
                    "ldmatrix.sync.aligned.m8n8.x4.shared.b16 {%0,%1,%2,%3}, [%4];"
                    : "=r"(a[mt][0]), "=r"(a[mt][1]), "=r"(a[mt][2]), "=r"(a[mt][3])
                    : "r"(addr));
            }
            uint32_t b[4][2];
#pragma unroll
            for (int half = 0; half < 2; half++) {
                uint32_t row = ks * 16 + (lane & 15);
                uint32_t gg  = wn * 4 + half * 2 + (lane >> 4);
                uint32_t addr = sB + sw_off(row, gg);
                uint32_t r0, r1, r2, r3;
                asm volatile(
                    "ldmatrix.sync.aligned.m8n8.x4.trans.shared.b16 {%0,%1,%2,%3}, [%4];"
                    : "=r"(r0), "=r"(r1), "=r"(r2), "=r"(r3)
                    : "r"(addr));
                b[half * 2 + 0][0] = r0; b[half * 2 + 0][1] = r1;
                b[half * 2 + 1][0] = r2; b[half * 2 + 1][1] = r3;
            }
#pragma unroll
            for (int mt = 0; mt < 2; mt++)
#pragma unroll
                for (int nt = 0; nt < 4; nt++) {
                    asm volatile(
                        "mma.sync.aligned.m16n8k16.row.col.f32.bf16.bf16.f32 "
                        "{%0,%1,%2,%3}, {%4,%5,%6,%7}, {%8,%9}, {%0,%1,%2,%3};"
                        : "+f"(acc[mt][nt][0]), "+f"(acc[mt][nt][1]),
                          "+f"(acc[mt][nt][2]), "+f"(acc[mt][nt][3])
                        : "r"(a[mt][0]), "r"(a[mt][1]), "r"(a[mt][2]), "r"(a[mt][3]),
                          "r"(b[nt][0]), "r"(b[nt][1]));
                }
        }
    }

    const int gsel = bn >> 2;
#pragma unroll
    for (int mt = 0; mt < 2; mt++) {
#pragma unroll
        for (int rr = 0; rr < 2; rr++) {
            int tok = bm * BM + wm * 32 + mt * 16 + (lane >> 2) + rr * 8;
            int grp = g_idx[tok * 2 + gsel];
            float* orow = out + (size_t)tok * DMODEL + grp * HDG;
#pragma unroll
            for (int nt = 0; nt < 4; nt++) {
                int c  = bn * BN + wn * 32 + nt * 8 + (lane & 3) * 2;
                int cl = c & (HDG - 1);
                float2 bv = *(const float2*)(bias + c);
                float2 v;
                v.x = acc[mt][nt][rr * 2 + 0] + bv.x;
                v.y = acc[mt][nt][rr * 2 + 1] + bv.y;
                *(float2*)(orow + cl) = v;
            }
        }
    }
}

// ---------------- launch ----------------
extern "C" void kernel_launch(void* const* d_in, const int* in_sizes, int n_in,
                              void* d_out, int out_size) {
    const float* x    = (const float*)d_in[0];
    const float* Wg   = (const float*)d_in[1];
    const float* Wm   = (const float*)d_in[2];
    const float* bias = (const float*)d_in[3];
    float* out = (float*)d_out;

    static bool attr_done = false;
    if (!attr_done) {
        cudaFuncSetAttribute(gate_kernel,
                             cudaFuncAttributeMaxDynamicSharedMemorySize, TOKPB * DMODEL * 4);
        cudaFuncSetAttribute(gemm_scatter,
                             cudaFuncAttributeMaxDynamicSharedMemorySize, 3 * STAGE_BYTES);
        attr_done = true;
    }

    gate_kernel<<<NTOK / TOKPB, 512, TOKPB * DMODEL * 4>>>(x, Wg, Wm, out);
    dim3 grid(DH / BN, NTOK / BM);
    gemm_scatter<<<grid, 256, 3 * STAGE_BYTES>>>(bias, out);
}

// round 14
// speedup vs baseline: 1.1288x; 1.0090x over previous
#include <cuda_runtime.h>
#include <cuda_bf16.h>
#include <cstdint>

#define NTOK 16384
#define DMODEL 2048
#define NGRP 8
#define HDG 256
#define DH 512   // k * hdg
#define TOKPB 8  // tokens per gate block

// ---------------- scratch (no allocs allowed) ----------------
__device__ __align__(16) __nv_bfloat16 g_hin[(size_t)NTOK * DH];   // 16 MB gathered, gated inputs
__device__ __align__(16) __nv_bfloat16 g_wm[(size_t)DH * DH];      // 512 KB bf16 weights ([k][n])
__device__ int g_idx[NTOK * 2];                                    // top-2 group indices per token

extern __shared__ __align__(16) unsigned char dynsmem[];

// ---------------- kernel 1 (R13): gate + passthrough + gather (+Wm convert) ----------------
// 8 tokens/block, 512 threads. Thread owns ONE gate group (tid&7) and 32
// x-elements (s=tid>>3): reduce needs only 2 shuffles/warp/token.
__global__ __launch_bounds__(512, 2) void gate_kernel(const float* __restrict__ x,
                                                      const float* __restrict__ Wg,
                                                      const float* __restrict__ Wm,
                                                      float* __restrict__ out) {
    float* xs = (float*)dynsmem;                      // [TOKPB][DMODEL] fp32
    __shared__ float wsum[TOKPB][16][NGRP];
    __shared__ float sG[TOKPB][2];
    __shared__ int   sI[TOKPB][2];

    const int tid  = threadIdx.x;
    const int lane = tid & 31;
    const int warp = tid >> 5;
    const int g    = tid & 7;    // this thread's gate group
    const int s    = tid >> 3;   // element-slice index, 0..63
    const size_t tok0 = (size_t)blockIdx.x * TOKPB;

    // stage 8 token rows via cp.async in two 32KB halves (tokens 0-3, 4-7)
    const uint32_t sx = (uint32_t)__cvta_generic_to_shared(xs);
    const float* src0 = x + tok0 * DMODEL;
#pragma unroll
    for (int i = 0; i < 4; i++) {
        int q = tid + i * 512;
        asm volatile("cp.async.cg.shared.global [%0], [%1], 16;\n"
                     :: "r"(sx + q * 16), "l"(src0 + q * 4));
    }
    asm volatile("cp.async.commit_group;\n");
#pragma unroll
    for (int i = 0; i < 4; i++) {
        int q = 2048 + tid + i * 512;
        asm volatile("cp.async.cg.shared.global [%0], [%1], 16;\n"
                     :: "r"(sx + q * 16), "l"(src0 + q * 4));
    }
    asm volatile("cp.async.commit_group;\n");

    // folded Wm fp32 -> bf16 conversion (blocks 0..511 cover all of Wm)
    if (blockIdx.x < 512) {
        int i = blockIdx.x * 512 + tid;
        g_wm[i] = __float2bfloat16(Wm[i]);
    }

    // Wg column-slice register cache: Wg[e][g] for e = k*256 + s*4 + c  (32 regs)
    float wgc[32];
#pragma unroll
    for (int k = 0; k < 8; k++)
#pragma unroll
        for (int c = 0; c < 4; c++)
            wgc[k * 4 + c] = __ldg(Wg + (size_t)(k * 256 + s * 4 + c) * NGRP + g);

    // first half arrived -> logits for tokens 0-3 while 4-7 still loading
    asm volatile("cp.async.wait_group 1;\n");
    __syncthreads();

#pragma unroll 2
    for (int t = 0; t < TOKPB / 2; t++) {
        const float4* xt = (const float4*)(xs + t * DMODEL);
        float a0 = 0.f, a1 = 0.f, a2 = 0.f, a3 = 0.f;
#pragma unroll
        for (int k = 0; k < 8; k++) {
            float4 v = xt[k * 64 + s];           // broadcast across 8 same-s lanes
            a0 += v.x * wgc[k * 4 + 0];
            a1 += v.y * wgc[k * 4 + 1];
            a2 += v.z * wgc[k * 4 + 2];
            a3 += v.w * wgc[k * 4 + 3];
        }
        float p = (a0 + a1) + (a2 + a3);
        p += __shfl_xor_sync(0xffffffffu, p, 8);
        p += __shfl_xor_sync(0xffffffffu, p, 16);
        if (lane < NGRP) wsum[t][warp][lane] = p;   // lane==g for lane<8
    }

    asm volatile("cp.async.wait_group 0;\n");
    __syncthreads();

#pragma unroll 2
    for (int t = TOKPB / 2; t < TOKPB; t++) {
        const float4* xt = (const float4*)(xs + t * DMODEL);
        float a0 = 0.f, a1 = 0.f, a2 = 0.f, a3 = 0.f;
#pragma unroll
        for (int k = 0; k < 8; k++) {
            float4 v = xt[k * 64 + s];
            a0 += v.x * wgc[k * 4 + 0];
            a1 += v.y * wgc[k * 4 + 1];
            a2 += v.z * wgc[k * 4 + 2];
            a3 += v.w * wgc[k * 4 + 3];
        }
        float p = (a0 + a1) + (a2 + a3);
        p += __shfl_xor_sync(0xffffffffu, p, 8);
        p += __shfl_xor_sync(0xffffffffu, p, 16);
        if (lane < NGRP) wsum[t][warp][lane] = p;
    }
    __syncthreads();

    // parallel partial reduce: 64 threads, one (token, group) pair each
    if (tid < 64) {
        int t = tid >> 3, j = tid & 7;
        float sum = 0.f;
#pragma unroll
        for (int w = 0; w < 16; w++) sum += wsum[t][w][j];
        wsum[t][0][j] = sum;
    }
    __syncthreads();

    // softmax + top-2, one token per lane (8 values each)
    if (tid < TOKPB) {
        int t = tid;
        float l[NGRP];
#pragma unroll
        for (int j = 0; j < NGRP; j++) l[j] = wsum[t][0][j];
        float m = l[0];
#pragma unroll
        for (int j = 1; j < NGRP; j++) m = fmaxf(m, l[j]);
        float e[NGRP], ssum = 0.f;
#pragma unroll
        for (int j = 0; j < NGRP; j++) { e[j] = expf(l[j] - m); ssum += e[j]; }
        int i0 = 0;
#pragma unroll
        for (int j = 1; j < NGRP; j++) if (e[j] > e[i0]) i0 = j;
        int i1 = (i0 == 0) ? 1 : 0;
#pragma unroll
        for (int j = 0; j < NGRP; j++) if (j != i0 && e[j] > e[i1]) i1 = j;
        float inv = 1.f / ssum;
        sG[t][0] = e[i0] * inv;  sG[t][1] = e[i1] * inv;
        sI[t][0] = i0;           sI[t][1] = i1;
        g_idx[(tok0 + t) * 2 + 0] = i0;
        g_idx[(tok0 + t) * 2 + 1] = i1;
    }
    __syncthreads();

    // passthrough (skip selected groups; GEMM writes those): 1 chunk/thread/token
#pragma unroll 1
    for (int t = 0; t < TOKPB; t++) {
        int i0 = sI[t][0], i1 = sI[t][1];
        int grp = tid >> 6;
        if (grp != i0 && grp != i1) {
            float4* orow = (float4*)(out + (tok0 + t) * DMODEL);
            __stcs(&orow[tid], ((const float4*)(xs + t * DMODEL))[tid]);
        }
    }
    // gather + gate -> g_hin: 2 tokens per pass, 256 threads each
#pragma unroll
    for (int it = 0; it < 4; it++) {
        int tloc = it * 2 + (tid >> 8);
        int p    = tid & 255;
        int half = p >> 7;
        float gate = sG[tloc][half];
        int base2 = sI[tloc][half] * (HDG / 2) + (p & 127);
        float2 xv = ((const float2*)(xs + tloc * DMODEL))[base2];
        ((__nv_bfloat162*)g_hin)[(tok0 + tloc) * (DH / 2) + p] =
            __floats2bfloat162_rn(gate * xv.x, gate * xv.y);
    }
}

// ---------------- kernel 2: GEMM [16384,512]x[512,512] bf16 -> fp32, scatter epilogue --------
// BM=128, BN=64, BK=64, 256 threads, 3-stage cp.async pipeline, 72KB dynamic smem.
// R6 rolled k-loop + pinned 3 blocks/SM.
#define BM 128
#define BN 64
#define BK 64
#define STAGE_BYTES (BM * BK * 2 + BK * BN * 2)   // 16KB + 8KB = 24KB

__device__ __forceinline__ uint32_t sw_off(uint32_t row, uint32_t g) {
    return row * 128u + ((g ^ (row & 7u)) * 16u);
}

__global__ __launch_bounds__(256, 3) void gemm_scatter(const float* __restrict__ bias,
                                                       float* __restrict__ out) {
    const int tid  = threadIdx.x;
    const int lane = tid & 31;
    const int warp = tid >> 5;
    const int wm   = warp >> 1;
    const int wn   = warp & 1;
    const int bn   = blockIdx.x;  // 0..7
    const int bm   = blockIdx.y;  // 0..127

    const __nv_bfloat16* Ag = g_hin + (size_t)(bm * BM) * DH;
    const __nv_bfloat16* Bg = g_wm + (size_t)(bn * BN);

    const uint32_t sBase = (uint32_t)__cvta_generic_to_shared(dynsmem);

    auto load_stage = [&](int s, int kt) {
        uint32_t sA = sBase + s * STAGE_BYTES;
        uint32_t sB = sA + BM * BK * 2;
#pragma unroll
        for (int i = 0; i < 4; i++) {
            int q = tid + i * 256;
            int r = q >> 3, g = q & 7;
            const __nv_bfloat16* src = Ag + (size_t)r * DH + kt + g * 8;
            asm volatile("cp.async.cg.shared.global [%0], [%1], 16;\n"
                         :: "r"(sA + sw_off(r, g)), "l"(src));
        }
#pragma unroll
        for (int i = 0; i < 2; i++) {
            int q = tid + i * 256;
            int r = q >> 3, g = q & 7;
            const __nv_bfloat16* src = Bg + (size_t)(kt + r) * DH + g * 8;
            asm volatile("cp.async.cg.shared.global [%0], [%1], 16;\n"
                         :: "r"(sB + sw_off(r, g)), "l"(src));
        }
        asm volatile("cp.async.commit_group;\n");
    };

    float acc[2][4][4];
#pragma unroll
    for (int a = 0; a < 2; a++)
#pragma unroll
        for (int b = 0; b < 4; b++)
#pragma unroll
            for (int c = 0; c < 4; c++) acc[a][b][c] = 0.f;

    const int NKT = DH / BK;   // 8
    load_stage(0, 0);
    load_stage(1, BK);

    for (int k = 0; k < NKT; k++) {
        if (k < NKT - 1) asm volatile("cp.async.wait_group 1;\n");
        else             asm volatile("cp.async.wait_group 0;\n");
        __syncthreads();

        if (k + 2 < NKT) load_stage((k + 2) % 3, (k + 2) * BK);

        uint32_t sA = sBase + (k % 3) * STAGE_BYTES;
        uint32_t sB = sA + BM * BK * 2;
#pragma unroll
        for (int ks = 0; ks < 4; ks++) {
            uint32_t a[2][4];
#pragma unroll
            for (int mt = 0; mt < 2; mt++) {
                uint32_t row = wm * 32 + mt * 16 + (lane & 15);
                uint32_t gg  = ks * 2 + (lane >> 4);
                uint32_t addr = sA + sw_off(row, gg);
                asm volatile(
                    "ldmatrix.sync.aligned.m8n8.x4.shared.b16 {%0,%1,%2,%3}, [%4];"
                    : "=r"(a[mt][0]), "=r"(a[mt][1]), "=r"(a[mt][2]), "=r"(a[mt][3])
                    : "r"(addr));
            }
            uint32_t b[4][2];
#pragma unroll
            for (int half = 0; half < 2; half++) {
                uint32_t row = ks * 16 + (lane & 15);
                uint32_t gg  = wn * 4 + half * 2 + (lane >> 4);
                uint32_t addr = sB + sw_off(row, gg);
                uint32_t r0, r1, r2, r3;
                asm volatile(
                    "ldmatrix.sync.aligned.m8n8.x4.trans.shared.b16 {%0,%1,%2,%3}, [%4];"
                    : "=r"(r0), "=r"(r1), "=r"(r2), "=r"(r3)
                    : "r"(addr));
                b[half * 2 + 0][0] = r0; b[half * 2 + 0][1] = r1;
                b[half * 2 + 1][0] = r2; b[half * 2 + 1][1] = r3;
            }
#pragma unroll
            for (int mt = 0; mt < 2; mt++)
#pragma unroll
                for (int nt = 0; nt < 4; nt++) {
                    asm volatile(
                        "mma.sync.aligned.m16n8k16.row.col.f32.bf16.bf16.f32 "
                        "{%0,%1,%2,%3}, {%4,%5,%6,%7}, {%8,%9}, {%0,%1,%2,%3};"
                        : "+f"(acc[mt][nt][0]), "+f"(acc[mt][nt][1]),
                          "+f"(acc[mt][nt][2]), "+f"(acc[mt][nt][3])
                        : "r"(a[mt][0]), "r"(a[mt][1]), "r"(a[mt][2]), "r"(a[mt][3]),
                          "r"(b[nt][0]), "r"(b[nt][1]));
                }
        }
    }

    const int gsel = bn >> 2;
#pragma unroll
    for (int mt = 0; mt < 2; mt++) {
#pragma unroll
        for (int rr = 0; rr < 2; rr++) {
            int tok = bm * BM + wm * 32 + mt * 16 + (lane >> 2) + rr * 8;
            int grp = g_idx[tok * 2 + gsel];
            float* orow = out + (size_t)tok * DMODEL + grp * HDG;
#pragma unroll
            for (int nt = 0; nt < 4; nt++) {
                int c  = bn * BN + wn * 32 + nt * 8 + (lane & 3) * 2;
                int cl = c & (HDG - 1);
                float2 bv = *(const float2*)(bias + c);
                float2 v;
                v.x = acc[mt][nt][rr * 2 + 0] + bv.x;
                v.y = acc[mt][nt][rr * 2 + 1] + bv.y;
                *(float2*)(orow + cl) = v;
            }
        }
    }
}

// ---------------- launch ----------------
extern "C" void kernel_launch(void* const* d_in, const int* in_sizes, int n_in,
                              void* d_out, int out_size) {
    const float* x    = (const float*)d_in[0];
    const float* Wg   = (const float*)d_in[1];
    const float* Wm   = (const float*)d_in[2];
    const float* bias = (const float*)d_in[3];
    float* out = (float*)d_out;

    static bool attr_done = false;
    if (!attr_done) {
        cudaFuncSetAttribute(gate_kernel,
                             cudaFuncAttributeMaxDynamicSharedMemorySize, TOKPB * DMODEL * 4);
        cudaFuncSetAttribute(gemm_scatter,
                             cudaFuncAttributeMaxDynamicSharedMemorySize, 3 * STAGE_BYTES);
        attr_done = true;
    }

    gate_kernel<<<NTOK / TOKPB, 512, TOKPB * DMODEL * 4>>>(x, Wg, Wm, out);
    dim3 grid(DH / BN, NTOK / BM);
    gemm_scatter<<<grid, 256, 3 * STAGE_BYTES>>>(bias, out);
}

// round 15
// speedup vs baseline: 1.1455x; 1.0148x over previous
#include <cuda_runtime.h>
#include <cuda_bf16.h>
#include <cstdint>

#define NTOK 16384
#define DMODEL 2048
#define NGRP 8
#define HDG 256
#define DH 512   // k * hdg
#define TOKPB 8  // tokens per gate block

// ---------------- scratch (no allocs allowed) ----------------
__device__ __align__(16) __nv_bfloat16 g_hin[(size_t)NTOK * DH];   // 16 MB gathered, gated inputs
__device__ __align__(16) __nv_bfloat16 g_wm[(size_t)DH * DH];      // 512 KB bf16 weights ([k][n])
__device__ int g_idx[NTOK * 2];                                    // top-2 group indices per token

extern __shared__ __align__(16) unsigned char dynsmem[];

// packed dual-fp32 FMA (Blackwell FFMA2): acc += v * w elementwise on f32x2
__device__ __forceinline__ void fma_f32x2(uint64_t& acc, uint64_t v, uint64_t w) {
    asm volatile("fma.rn.f32x2 %0, %1, %2, %0;" : "+l"(acc) : "l"(v), "l"(w));
}

// ---------------- kernel 1: gate + passthrough + gather (+Wm convert) ----------------------
// 8 tokens/block, 512 threads. Thread owns ONE gate group (tid&7) and 32
// x-elements (s=tid>>3). Logit inner loop uses packed f32x2 FMAs (2 MACs/instr).
__global__ __launch_bounds__(512, 2) void gate_kernel(const float* __restrict__ x,
                                                      const float* __restrict__ Wg,
                                                      const float* __restrict__ Wm,
                                                      float* __restrict__ out) {
    float* xs = (float*)dynsmem;                      // [TOKPB][DMODEL] fp32
    __shared__ float wsum[TOKPB][16][NGRP];
    __shared__ float sG[TOKPB][2];
    __shared__ int   sI[TOKPB][2];

    const int tid  = threadIdx.x;
    const int lane = tid & 31;
    const int warp = tid >> 5;
    const int g    = tid & 7;    // this thread's gate group
    const int s    = tid >> 3;   // element-slice index, 0..63
    const size_t tok0 = (size_t)blockIdx.x * TOKPB;

    // stage 8 token rows via cp.async in two 32KB halves (tokens 0-3, 4-7)
    const uint32_t sx = (uint32_t)__cvta_generic_to_shared(xs);
    const float* src0 = x + tok0 * DMODEL;
#pragma unroll
    for (int i = 0; i < 4; i++) {
        int q = tid + i * 512;
        asm volatile("cp.async.cg.shared.global [%0], [%1], 16;\n"
                     :: "r"(sx + q * 16), "l"(src0 + q * 4));
    }
    asm volatile("cp.async.commit_group;\n");
#pragma unroll
    for (int i = 0; i < 4; i++) {
        int q = 2048 + tid + i * 512;
        asm volatile("cp.async.cg.shared.global [%0], [%1], 16;\n"
                     :: "r"(sx + q * 16), "l"(src0 + q * 4));
    }
    asm volatile("cp.async.commit_group;\n");

    // folded Wm fp32 -> bf16 conversion (blocks 0..511 cover all of Wm)
    if (blockIdx.x < 512) {
        int i = blockIdx.x * 512 + tid;
        g_wm[i] = __float2bfloat16(Wm[i]);
    }

    // Wg column-slice register cache, packed as f32x2 pairs:
    // wp[2k]   = (Wg[e0][g], Wg[e1][g]),  wp[2k+1] = (Wg[e2][g], Wg[e3][g]),
    // where e_c = k*256 + s*4 + c
    uint64_t wp[16];
#pragma unroll
    for (int k = 0; k < 8; k++) {
        float2 w01, w23;
        w01.x = __ldg(Wg + (size_t)(k * 256 + s * 4 + 0) * NGRP + g);
        w01.y = __ldg(Wg + (size_t)(k * 256 + s * 4 + 1) * NGRP + g);
        w23.x = __ldg(Wg + (size_t)(k * 256 + s * 4 + 2) * NGRP + g);
        w23.y = __ldg(Wg + (size_t)(k * 256 + s * 4 + 3) * NGRP + g);
        wp[2 * k]     = *(uint64_t*)&w01;
        wp[2 * k + 1] = *(uint64_t*)&w23;
    }

    // first half arrived -> logits for tokens 0-3 while 4-7 still loading
    asm volatile("cp.async.wait_group 1;\n");
    __syncthreads();

#pragma unroll 2
    for (int t = 0; t < TOKPB / 2; t++) {
        const float4* xt = (const float4*)(xs + t * DMODEL);
        uint64_t acc01 = 0ull, acc23 = 0ull;   // packed (0.f, 0.f)
#pragma unroll
        for (int k = 0; k < 8; k++) {
            float4 v = xt[k * 64 + s];          // broadcast across 8 same-s lanes
            fma_f32x2(acc01, *(uint64_t*)&v.x, wp[2 * k]);
            fma_f32x2(acc23, *(uint64_t*)&v.z, wp[2 * k + 1]);
        }
        uint64_t accs;
        asm volatile("add.rn.f32x2 %0, %1, %2;" : "=l"(accs) : "l"(acc01), "l"(acc23));
        float2 rr = *(float2*)&accs;
        float p = rr.x + rr.y;
        p += __shfl_xor_sync(0xffffffffu, p, 8);
        p += __shfl_xor_sync(0xffffffffu, p, 16);
        if (lane < NGRP) wsum[t][warp][lane] = p;   // lane==g for lane<8
    }

    asm volatile("cp.async.wait_group 0;\n");
    __syncthreads();

#pragma unroll 2
    for (int t = TOKPB / 2; t < TOKPB; t++) {
        const float4* xt = (const float4*)(xs + t * DMODEL);
        uint64_t acc01 = 0ull, acc23 = 0ull;
#pragma unroll
        for (int k = 0; k < 8; k++) {
            float4 v = xt[k * 64 + s];
            fma_f32x2(acc01, *(uint64_t*)&v.x, wp[2 * k]);
            fma_f32x2(acc23, *(uint64_t*)&v.z, wp[2 * k + 1]);
        }
        uint64_t accs;
        asm volatile("add.rn.f32x2 %0, %1, %2;" : "=l"(accs) : "l"(acc01), "l"(acc23));
        float2 rr = *(float2*)&accs;
        float p = rr.x + rr.y;
        p += __shfl_xor_sync(0xffffffffu, p, 8);
        p += __shfl_xor_sync(0xffffffffu, p, 16);
        if (lane < NGRP) wsum[t][warp][lane] = p;
    }
    __syncthreads();

    // parallel partial reduce: 64 threads, one (token, group) pair each
    if (tid < 64) {
        int t = tid >> 3, j = tid & 7;
        float sum = 0.f;
#pragma unroll
        for (int w = 0; w < 16; w++) sum += wsum[t][w][j];
        wsum[t][0][j] = sum;
    }
    __syncthreads();

    // softmax + top-2, one token per lane (8 values each)
    if (tid < TOKPB) {
        int t = tid;
        float l[NGRP];
#pragma unroll
        for (int j = 0; j < NGRP; j++) l[j] = wsum[t][0][j];
        float m = l[0];
#pragma unroll
        for (int j = 1; j < NGRP; j++) m = fmaxf(m, l[j]);
        float e[NGRP], ssum = 0.f;
#pragma unroll
        for (int j = 0; j < NGRP; j++) { e[j] = expf(l[j] - m); ssum += e[j]; }
        int i0 = 0;
#pragma unroll
        for (int j = 1; j < NGRP; j++) if (e[j] > e[i0]) i0 = j;
        int i1 = (i0 == 0) ? 1 : 0;
#pragma unroll
        for (int j = 0; j < NGRP; j++) if (j != i0 && e[j] > e[i1]) i1 = j;
        float inv = 1.f / ssum;
        sG[t][0] = e[i0] * inv;  sG[t][1] = e[i1] * inv;
        sI[t][0] = i0;           sI[t][1] = i1;
        g_idx[(tok0 + t) * 2 + 0] = i0;
        g_idx[(tok0 + t) * 2 + 1] = i1;
    }
    __syncthreads();

    // passthrough (skip selected groups; GEMM writes those): 1 chunk/thread/token
#pragma unroll 1
    for (int t = 0; t < TOKPB; t++) {
        int i0 = sI[t][0], i1 = sI[t][1];
        int grp = tid >> 6;
        if (grp != i0 && grp != i1) {
            float4* orow = (float4*)(out + (tok0 + t) * DMODEL);
            __stcs(&orow[tid], ((const float4*)(xs + t * DMODEL))[tid]);
        }
    }
    // gather + gate -> g_hin: 2 tokens per pass, 256 threads each
#pragma unroll
    for (int it = 0; it < 4; it++) {
        int tloc = it * 2 + (tid >> 8);
        int p    = tid & 255;
        int half = p >> 7;
        float gate = sG[tloc][half];
        int base2 = sI[tloc][half] * (HDG / 2) + (p & 127);
        float2 xv = ((const float2*)(xs + tloc * DMODEL))[base2];
        ((__nv_bfloat162*)g_hin)[(tok0 + tloc) * (DH / 2) + p] =
            __floats2bfloat162_rn(gate * xv.x, gate * xv.y);
    }
}

// ---------------- kernel 2 (R14): GEMM [16384,512]x[512,512] bf16, scatter epilogue --------
// BM=128, BN=64, BK=64, 256 threads, 3-stage cp.async pipeline, 72KB dynamic smem.
#define BM 128
#define BN 64
#define BK 64
#define STAGE_BYTES (BM * BK * 2 + BK * BN * 2)   // 16KB + 8KB = 24KB

__device__ __forceinline__ uint32_t sw_off(uint32_t row, uint32_t g) {
    return row * 128u + ((g ^ (row & 7u)) * 16u);
}

__global__ __launch_bounds__(256, 3) void gemm_scatter(const float* __restrict__ bias,
                                                       float* __restrict__ out) {
    const int tid  = threadIdx.x;
    const int lane = tid & 31;
    const int warp = tid >> 5;
    const int wm   = warp >> 1;
    const int wn   = warp & 1;
    const int bn   = blockIdx.x;  // 0..7
    const int bm   = blockIdx.y;  // 0..127

    const __nv_bfloat16* Ag = g_hin + (size_t)(bm * BM) * DH;
    const __nv_bfloat16* Bg = g_wm + (size_t)(bn * BN);

    const uint32_t sBase = (uint32_t)__cvta_generic_to_shared(dynsmem);

    auto load_stage = [&](int s, int kt) {
        uint32_t sA = sBase + s * STAGE_BYTES;
        uint32_t sB = sA + BM * BK * 2;
#pragma unroll
        for (int i = 0; i < 4; i++) {
            int q = tid + i * 256;
            int r = q >> 3, g = q & 7;
            const __nv_bfloat16* src = Ag + (size_t)r * DH + kt + g * 8;
            asm volatile("cp.async.cg.shared.global [%0], [%1], 16;\n"
                         :: "r"(sA + sw_off(r, g)), "l"(src));
        }
#pragma unroll
        for (int i = 0; i < 2; i++) {
            int q = tid + i * 256;
            int r = q >> 3, g = q & 7;
            const __nv_bfloat16* src = Bg + (size_t)(kt + r) * DH + g * 8;
            asm volatile("cp.async.cg.shared.global [%0], [%1], 16;\n"
                         :: "r"(sB + sw_off(r, g)), "l"(src));
        }
        asm volatile("cp.async.commit_group;\n");
    };

    float acc[2][4][4];
#pragma unroll
    for (int a = 0; a < 2; a++)
#pragma unroll
        for (int b = 0; b < 4; b++)
#pragma unroll
            for (int c = 0; c < 4; c++) acc[a][b][c] = 0.f;

    const int NKT = DH / BK;   // 8
    load_stage(0, 0);
    load_stage(1, BK);

    for (int k = 0; k < NKT; k++) {
        if (k < NKT - 1) asm volatile("cp.async.wait_group 1;\n");
        else             asm volatile("cp.async.wait_group 0;\n");
        __syncthreads();

        if (k + 2 < NKT) load_stage((k + 2) % 3, (k + 2) * BK);

        uint32_t sA = sBase + (k % 3) * STAGE_BYTES;
        uint32_t sB = sA + BM * BK * 2;
#pragma unroll
        for (int ks = 0; ks < 4; ks++) {
            uint32_t a[2][4];
#pragma unroll
            for (int mt = 0; mt < 2; mt++) {
                uint32_t row = wm * 32 + mt * 16 + (lane & 15);
                uint32_t gg  = ks * 2 + (lane >> 4);
                uint32_t addr = sA + sw_off(row, gg);
                asm volatile(
                    "ldmatrix.sync.aligned.m8n8.x4.shared.b16 {%0,%1,%2,%3}, [%4];"
                    : "=r"(a[mt][0]), "=r"(a[mt][1]), "=r"(a[mt][2]), "=r"(a[mt][3])
                    : "r"(addr));
            }
            uint32_t b[4][2];
#pragma unroll
            for (int half = 0; half < 2; half++) {
                uint32_t row = ks * 16 + (lane & 15);
                uint32_t gg  = wn * 4 + half * 2 + (lane >> 4);
                uint32_t addr = sB + sw_off(row, gg);
                uint32_t r0, r1, r2, r3;
                asm volatile(
                    "ldmatrix.sync.aligned.m8n8.x4.trans.shared.b16 {%0,%1,%2,%3}, [%4];"
                    : "=r"(r0), "=r"(r1), "=r"(r2), "=r"(r3)
                    : "r"(addr));
                b[half * 2 + 0][0] = r0; b[half * 2 + 0][1] = r1;
                b[half * 2 + 1][0] = r2; b[half * 2 + 1][1] = r3;
            }
#pragma unroll
            for (int mt = 0; mt < 2; mt++)
#pragma unroll
                for (int nt = 0; nt < 4; nt++) {
                    asm volatile(
                        "mma.sync.aligned.m16n8k16.row.col.f32.bf16.bf16.f32 "
                        "{%0,%1,%2,%3}, {%4,%5,%6,%7}, {%8,%9}, {%0,%1,%2,%3};"
                        : "+f"(acc[mt][nt][0]), "+f"(acc[mt][nt][1]),
                          "+f"(acc[mt][nt][2]), "+f"(acc[mt][nt][3])
                        : "r"(a[mt][0]), "r"(a[mt][1]), "r"(a[mt][2]), "r"(a[mt][3]),
                          "r"(b[nt][0]), "r"(b[nt][1]));
                }
        }
    }

    const int gsel = bn >> 2;
#pragma unroll
    for (int mt = 0; mt < 2; mt++) {
#pragma unroll
        for (int rr = 0; rr < 2; rr++) {
            int tok = bm * BM + wm * 32 + mt * 16 + (lane >> 2) + rr * 8;
            int grp = g_idx[tok * 2 + gsel];
            float* orow = out + (size_t)tok * DMODEL + grp * HDG;
#pragma unroll
            for (int nt = 0; nt < 4; nt++) {
                int c  = bn * BN + wn * 32 + nt * 8 + (lane & 3) * 2;
                int cl = c & (HDG - 1);
                float2 bv = *(const float2*)(bias + c);
                float2 v;
                v.x = acc[mt][nt][rr * 2 + 0] + bv.x;
                v.y = acc[mt][nt][rr * 2 + 1] + bv.y;
                *(float2*)(orow + cl) = v;
            }
        }
    }
}

// ---------------- launch ----------------
extern "C" void kernel_launch(void* const* d_in, const int* in_sizes, int n_in,
                              void* d_out, int out_size) {
    const float* x    = (const float*)d_in[0];
    const float* Wg   = (const float*)d_in[1];
    const float* Wm   = (const float*)d_in[2];
    const float* bias = (const float*)d_in[3];
    float* out = (float*)d_out;

    static bool attr_done = false;
    if (!attr_done) {
        cudaFuncSetAttribute(gate_kernel,
                             cudaFuncAttributeMaxDynamicSharedMemorySize, TOKPB * DMODEL * 4);
        cudaFuncSetAttribute(gemm_scatter,
                             cudaFuncAttributeMaxDynamicSharedMemorySize, 3 * STAGE_BYTES);
        attr_done = true;
    }

    gate_kernel<<<NTOK / TOKPB, 512, TOKPB * DMODEL * 4>>>(x, Wg, Wm, out);
    dim3 grid(DH / BN, NTOK / BM);
    gemm_scatter<<<grid, 256, 3 * STAGE_BYTES>>>(bias, out);
}